// round 2
// baseline (speedup 1.0000x reference)
#include <cuda_runtime.h>
#include <cstdint>

// MLP: 64 -> 4 -> 8 -> 8 -> 32, sigmoid after each layer. fp32. Batch 1M.
// DRAM floor ~55us (256MB in + 128MB out @ ~7TB/s).
// Structure: persistent blocks, double-buffered cp.async tile pipeline,
// per-row compute for layers 0-2, h2 exchanged via smem, layer 3 computed
// in the coalesced output domain with direct STG.128.

#define TPB 128           // threads (= rows) per tile
#define XPAD 17           // float4 per padded x row (16 data + 1 pad)
#define H2STRIDE 3        // float4 per h2 row (2 data + 1 pad) -> 12 floats

// shared weight layout (float offsets)
#define OFF_W0 0      // [4][64]   256
#define OFF_B0 256    // [4]
#define OFF_W1 260    // [8][4]    32
#define OFF_B1 292    // [8]
#define OFF_W2 300    // [8][8]    64
#define OFF_B2 364    // [8]
#define OFF_W3 372    // [32][8]   256
#define OFF_B3 628    // [32]
#define W_TOT  660

#define TILE_F4   (TPB * XPAD)               // float4 per x buffer
#define SMEM_F4   (2 * TILE_F4 + TPB * H2STRIDE)
#define SMEM_BYTES (SMEM_F4 * 16 + W_TOT * 4)

__device__ __forceinline__ float sigmoidf_fast(float x) {
    return __fdividef(1.0f, 1.0f + __expf(-x));
}

__device__ __forceinline__ float dot4(float4 a, float4 b) {
    float s = a.x * b.x;
    s = fmaf(a.y, b.y, s);
    s = fmaf(a.z, b.z, s);
    s = fmaf(a.w, b.w, s);
    return s;
}

__device__ __forceinline__ void cp_async16(uint32_t smem_addr, const void* gptr) {
    asm volatile("cp.async.cg.shared.global [%0], [%1], 16;\n"
                 :: "r"(smem_addr), "l"(gptr));
}
__device__ __forceinline__ void cp_commit() {
    asm volatile("cp.async.commit_group;\n" ::: "memory");
}
__device__ __forceinline__ void cp_wait1() {
    asm volatile("cp.async.wait_group 1;\n" ::: "memory");
}

// prefetch one 128x64 float tile (as 16 float4 per row) into buf
__device__ __forceinline__ void prefetch_tile(const float4* __restrict__ x4,
                                              float4* buf, int tile, int lim4, int tid)
{
    const int base4 = tile * (TPB * 16);
    #pragma unroll
    for (int it = 0; it < 16; ++it) {
        int local = it * TPB + tid;
        int idx = base4 + local;
        if (idx < lim4) {
            int r = local >> 4;
            int c = local & 15;
            uint32_t dst = (uint32_t)__cvta_generic_to_shared(&buf[r * XPAD + c]);
            cp_async16(dst, (const void*)(x4 + idx));
        }
    }
}

__global__ void __launch_bounds__(TPB)
mlp_kernel(const float* __restrict__ x,
           const float* __restrict__ W0, const float* __restrict__ b0,
           const float* __restrict__ W1, const float* __restrict__ b1,
           const float* __restrict__ W2, const float* __restrict__ b2,
           const float* __restrict__ W3, const float* __restrict__ b3,
           float* __restrict__ out, int batch)
{
    extern __shared__ __align__(16) float4 smem[];
    float4* buf0 = smem;
    float4* buf1 = smem + TILE_F4;
    float4* h2s  = smem + 2 * TILE_F4;              // TPB * H2STRIDE float4
    float*  sW   = (float*)(smem + SMEM_F4);        // W_TOT floats

    const int tid = threadIdx.x;

    // ---- weights into shared (visible after first in-loop __syncthreads) ----
    for (int i = tid; i < 256; i += TPB) sW[OFF_W0 + i] = W0[i];
    if (tid < 4)  sW[OFF_B0 + tid] = b0[tid];
    if (tid < 32) sW[OFF_W1 + tid] = W1[tid];
    if (tid < 8)  sW[OFF_B1 + tid] = b1[tid];
    if (tid < 64) sW[OFF_W2 + tid] = W2[tid];
    if (tid < 8)  sW[OFF_B2 + tid] = b2[tid];
    for (int i = tid; i < 256; i += TPB) sW[OFF_W3 + i] = W3[i];
    if (tid < 32) sW[OFF_B3 + tid] = b3[tid];

    const float4* __restrict__ x4 = (const float4*)x;
    float4* __restrict__ out4 = (float4*)out;
    const int lim4  = batch * 16;     // float4 count of x
    const int olim4 = batch * 8;      // float4 count of out
    const int numTiles = (batch + TPB - 1) / TPB;

    int t = blockIdx.x;
    if (t >= numTiles) return;

    // initial prefetch
    prefetch_tile(x4, buf0, t, lim4, tid);
    cp_commit();
    int cur = 0;

    while (true) {
        const int tn = t + gridDim.x;
        float4* bufc = cur ? buf1 : buf0;
        float4* bufn = cur ? buf0 : buf1;

        // prefetch next tile (possibly empty group)
        if (tn < numTiles) prefetch_tile(x4, bufn, tn, lim4, tid);
        cp_commit();
        cp_wait1();                 // current tile resident
        __syncthreads();            // + weights visible (first iter)

        const int row = t * TPB + tid;
        const bool active = (row < batch);
        float h2[8];

        if (active) {
            // ---- layer 0: 64 -> 4 ----
            float acc0[4];
            #pragma unroll
            for (int j = 0; j < 4; ++j) acc0[j] = sW[OFF_B0 + j];
            const float4* myrow = &bufc[tid * XPAD];
            #pragma unroll
            for (int c = 0; c < 16; ++c) {
                float4 xv = myrow[c];
                #pragma unroll
                for (int j = 0; j < 4; ++j) {
                    float4 w = *(const float4*)&sW[OFF_W0 + j * 64 + c * 4];
                    acc0[j] = fmaf(xv.x, w.x, acc0[j]);
                    acc0[j] = fmaf(xv.y, w.y, acc0[j]);
                    acc0[j] = fmaf(xv.z, w.z, acc0[j]);
                    acc0[j] = fmaf(xv.w, w.w, acc0[j]);
                }
            }
            float4 h0;
            h0.x = sigmoidf_fast(acc0[0]);
            h0.y = sigmoidf_fast(acc0[1]);
            h0.z = sigmoidf_fast(acc0[2]);
            h0.w = sigmoidf_fast(acc0[3]);

            // ---- layer 1: 4 -> 8 ----
            float h1[8];
            #pragma unroll
            for (int j = 0; j < 8; ++j) {
                float4 w = *(const float4*)&sW[OFF_W1 + j * 4];
                h1[j] = sigmoidf_fast(sW[OFF_B1 + j] + dot4(h0, w));
            }

            // ---- layer 2: 8 -> 8 ----
            float4 ha = make_float4(h1[0], h1[1], h1[2], h1[3]);
            float4 hb = make_float4(h1[4], h1[5], h1[6], h1[7]);
            #pragma unroll
            for (int j = 0; j < 8; ++j) {
                float4 wa = *(const float4*)&sW[OFF_W2 + j * 8];
                float4 wb = *(const float4*)&sW[OFF_W2 + j * 8 + 4];
                h2[j] = sigmoidf_fast(sW[OFF_B2 + j] + dot4(ha, wa) + dot4(hb, wb));
            }
        }

        // exchange h2; this barrier also releases bufc for the next prefetch
        __syncthreads();
        h2s[tid * H2STRIDE + 0] = make_float4(h2[0], h2[1], h2[2], h2[3]);
        h2s[tid * H2STRIDE + 1] = make_float4(h2[4], h2[5], h2[6], h2[7]);
        __syncthreads();

        // ---- layer 3 in coalesced domain: thread computes the float4 it stores
        const int obase4 = t * (TPB * 8);
        #pragma unroll
        for (int it = 0; it < 8; ++it) {
            int local = it * TPB + tid;
            int gidx = obase4 + local;
            if (gidx < olim4) {
                int r  = local >> 3;   // row within tile
                int c4 = local & 7;    // which float4 of the 8 output float4s
                float4 ra = h2s[r * H2STRIDE + 0];
                float4 rb = h2s[r * H2STRIDE + 1];
                float o[4];
                #pragma unroll
                for (int k = 0; k < 4; ++k) {
                    int j = c4 * 4 + k;
                    float4 wa = *(const float4*)&sW[OFF_W3 + j * 8];
                    float4 wb = *(const float4*)&sW[OFF_W3 + j * 8 + 4];
                    o[k] = sigmoidf_fast(sW[OFF_B3 + j] + dot4(ra, wa) + dot4(rb, wb));
                }
                out4[gidx] = make_float4(o[0], o[1], o[2], o[3]);
            }
        }

        if (tn >= numTiles) break;
        t = tn;
        cur ^= 1;
    }
}

extern "C" void kernel_launch(void* const* d_in, const int* in_sizes, int n_in,
                              void* d_out, int out_size)
{
    const float* x  = (const float*)d_in[0];
    const float* W0 = (const float*)d_in[1];
    const float* b0 = (const float*)d_in[2];
    const float* W1 = (const float*)d_in[3];
    const float* b1 = (const float*)d_in[4];
    const float* W2 = (const float*)d_in[5];
    const float* b2 = (const float*)d_in[6];
    const float* W3 = (const float*)d_in[7];
    const float* b3 = (const float*)d_in[8];
    float* out = (float*)d_out;

    int batch = in_sizes[0] / 64;
    int numTiles = (batch + TPB - 1) / TPB;

    static bool attr_set = false;
    if (!attr_set) {
        cudaFuncSetAttribute(mlp_kernel,
                             cudaFuncAttributeMaxDynamicSharedMemorySize,
                             SMEM_BYTES);
        attr_set = true;
    }

    int grid = 296;                       // 2 blocks per SM (148 SMs), persistent
    if (grid > numTiles) grid = numTiles;

    mlp_kernel<<<grid, TPB, SMEM_BYTES>>>(x, W0, b0, W1, b1, W2, b2, W3, b3,
                                          out, batch);
}

// round 3
// speedup vs baseline: 2.3056x; 2.3056x over previous
#include <cuda_runtime.h>

// MLP 64->4->8->8->32, sigmoid each layer, fp32, batch 1M. DRAM-bound (384MB).
// Warp-level dataflow, no x/out smem staging:
//   - layer 0 computed in the coalesced-load domain (W0 fragment in regs,
//     shfl_xor reduce over 16 lanes, capture shuffle -> row owner thread)
//   - layers 1-2 per-row, weights broadcast from tiny smem array
//   - layer 3 computed in the coalesced-store domain (W3 fragment in regs,
//     h2 redistributed by shuffles), direct STG.128

#define TPB 256

__device__ __forceinline__ float sigmoidf_fast(float x) {
    return __fdividef(1.0f, 1.0f + __expf(-x));
}

__device__ __forceinline__ float dot4(float4 a, float4 b) {
    float s = a.x * b.x;
    s = fmaf(a.y, b.y, s);
    s = fmaf(a.z, b.z, s);
    s = fmaf(a.w, b.w, s);
    return s;
}

__global__ void __launch_bounds__(TPB, 2)
mlp_kernel(const float* __restrict__ x,
           const float* __restrict__ W0, const float* __restrict__ b0,
           const float* __restrict__ W1, const float* __restrict__ b1,
           const float* __restrict__ W2, const float* __restrict__ b2,
           const float* __restrict__ W3, const float* __restrict__ b3,
           float* __restrict__ out, int batch)
{
    __shared__ __align__(16) float sW1[32];
    __shared__ __align__(16) float sB1[8];
    __shared__ __align__(16) float sW2[64];
    __shared__ __align__(16) float sB2[8];

    const int tid  = threadIdx.x;
    const int lane = tid & 31;

    if (tid < 32)                sW1[tid]       = W1[tid];
    else if (tid < 40)           sB1[tid - 32]  = b1[tid - 32];
    else if (tid >= 64 && tid < 128) sW2[tid - 64] = W2[tid - 64];
    else if (tid >= 128 && tid < 136) sB2[tid - 128] = b2[tid - 128];

    // ---- per-thread register weights ----
    const int c  = lane & 15;   // layer-0 column fragment owned by this lane
    const int c4 = lane & 7;    // output float4 index owned by this lane

    float4 w0f[4];
    #pragma unroll
    for (int j = 0; j < 4; ++j)
        w0f[j] = *(const float4*)(W0 + j * 64 + c * 4);
    const float4 b0v = *(const float4*)b0;

    float4 w3a[4], w3b[4];
    float  b3f[4];
    #pragma unroll
    for (int kk = 0; kk < 4; ++kk) {
        int j = c4 * 4 + kk;
        w3a[kk] = *(const float4*)(W3 + j * 8);
        w3b[kk] = *(const float4*)(W3 + j * 8 + 4);
        b3f[kk] = b3[j];
    }
    __syncthreads();

    const int warp    = blockIdx.x * (TPB / 32) + (tid >> 5);
    const int rowbase = warp * 32;
    if (rowbase >= batch) return;

    if (rowbase + 32 <= batch) {
        // ======================= fast path: full warp =======================
        const float4* __restrict__ xw = (const float4*)x + (size_t)rowbase * 16;

        // ---- load + layer 0: coalesced domain ----
        float a0 = 0.f, a1 = 0.f, a2 = 0.f, a3 = 0.f;
        #pragma unroll
        for (int i = 0; i < 16; ++i) {
            float4 v = xw[i * 32 + lane];       // fully coalesced LDG.128
            float p0 = dot4(v, w0f[0]);
            float p1 = dot4(v, w0f[1]);
            float p2 = dot4(v, w0f[2]);
            float p3 = dot4(v, w0f[3]);
            #pragma unroll
            for (int s = 1; s < 16; s <<= 1) {
                p0 += __shfl_xor_sync(0xffffffffu, p0, s);
                p1 += __shfl_xor_sync(0xffffffffu, p1, s);
                p2 += __shfl_xor_sync(0xffffffffu, p2, s);
                p3 += __shfl_xor_sync(0xffffffffu, p3, s);
            }
            // rows this iteration: 2i (lanes 0-15), 2i+1 (lanes 16-31).
            // thread `lane` owns row rowbase+lane -> capture at i == lane>>1
            // from source half (lane&1).
            const int src = (lane & 1) << 4;
            float q0 = __shfl_sync(0xffffffffu, p0, src);
            float q1 = __shfl_sync(0xffffffffu, p1, src);
            float q2 = __shfl_sync(0xffffffffu, p2, src);
            float q3 = __shfl_sync(0xffffffffu, p3, src);
            if ((lane >> 1) == i) { a0 = q0; a1 = q1; a2 = q2; a3 = q3; }
        }

        float4 h0;
        h0.x = sigmoidf_fast(a0 + b0v.x);
        h0.y = sigmoidf_fast(a1 + b0v.y);
        h0.z = sigmoidf_fast(a2 + b0v.z);
        h0.w = sigmoidf_fast(a3 + b0v.w);

        // ---- layer 1: 4 -> 8 (weights broadcast from smem) ----
        float h1[8];
        #pragma unroll
        for (int j = 0; j < 8; ++j) {
            float4 w = *(const float4*)&sW1[j * 4];
            h1[j] = sigmoidf_fast(sB1[j] + dot4(h0, w));
        }
        float4 ha = make_float4(h1[0], h1[1], h1[2], h1[3]);
        float4 hb = make_float4(h1[4], h1[5], h1[6], h1[7]);

        // ---- layer 2: 8 -> 8 ----
        float h2[8];
        #pragma unroll
        for (int j = 0; j < 8; ++j) {
            float4 wa = *(const float4*)&sW2[j * 8];
            float4 wb = *(const float4*)&sW2[j * 8 + 4];
            h2[j] = sigmoidf_fast(sB2[j] + dot4(ha, wa) + dot4(hb, wb));
        }

        // ---- layer 3: coalesced-store domain ----
        float4* __restrict__ ow = (float4*)out + (size_t)rowbase * 8;
        #pragma unroll
        for (int k = 0; k < 8; ++k) {
            // this thread stores out float4 (k*32 + lane):
            //   row = 4k + (lane>>3), fragment c4 = lane&7
            const int srcl = 4 * k + (lane >> 3);
            float hh0 = __shfl_sync(0xffffffffu, h2[0], srcl);
            float hh1 = __shfl_sync(0xffffffffu, h2[1], srcl);
            float hh2 = __shfl_sync(0xffffffffu, h2[2], srcl);
            float hh3 = __shfl_sync(0xffffffffu, h2[3], srcl);
            float hh4 = __shfl_sync(0xffffffffu, h2[4], srcl);
            float hh5 = __shfl_sync(0xffffffffu, h2[5], srcl);
            float hh6 = __shfl_sync(0xffffffffu, h2[6], srcl);
            float hh7 = __shfl_sync(0xffffffffu, h2[7], srcl);
            float4 ga = make_float4(hh0, hh1, hh2, hh3);
            float4 gb = make_float4(hh4, hh5, hh6, hh7);
            float o[4];
            #pragma unroll
            for (int kk = 0; kk < 4; ++kk)
                o[kk] = sigmoidf_fast(b3f[kk] + dot4(ga, w3a[kk]) + dot4(gb, w3b[kk]));
            ow[k * 32 + lane] = make_float4(o[0], o[1], o[2], o[3]);
        }
    } else {
        // =================== slow path: partial warp (tail) ===================
        const int row = rowbase + lane;
        if (row < batch) {
            const float* xr = x + (size_t)row * 64;
            float h0[4];
            #pragma unroll
            for (int j = 0; j < 4; ++j) {
                float s = b0[j];
                for (int k = 0; k < 64; ++k) s = fmaf(xr[k], W0[j * 64 + k], s);
                h0[j] = sigmoidf_fast(s);
            }
            float h1[8];
            #pragma unroll
            for (int j = 0; j < 8; ++j) {
                float s = b1[j];
                for (int k = 0; k < 4; ++k) s = fmaf(h0[k], W1[j * 4 + k], s);
                h1[j] = sigmoidf_fast(s);
            }
            float h2[8];
            #pragma unroll
            for (int j = 0; j < 8; ++j) {
                float s = b2[j];
                for (int k = 0; k < 8; ++k) s = fmaf(h1[k], W2[j * 8 + k], s);
                h2[j] = sigmoidf_fast(s);
            }
            float* orow = out + (size_t)row * 32;
            #pragma unroll
            for (int j = 0; j < 32; ++j) {
                float s = b3[j];
                for (int k = 0; k < 8; ++k) s = fmaf(h2[k], W3[j * 8 + k], s);
                orow[j] = sigmoidf_fast(s);
            }
        }
    }
}

extern "C" void kernel_launch(void* const* d_in, const int* in_sizes, int n_in,
                              void* d_out, int out_size)
{
    const float* x  = (const float*)d_in[0];
    const float* W0 = (const float*)d_in[1];
    const float* b0 = (const float*)d_in[2];
    const float* W1 = (const float*)d_in[3];
    const float* b1 = (const float*)d_in[4];
    const float* W2 = (const float*)d_in[5];
    const float* b2 = (const float*)d_in[6];
    const float* W3 = (const float*)d_in[7];
    const float* b3 = (const float*)d_in[8];
    float* out = (float*)d_out;

    int batch = in_sizes[0] / 64;
    int grid = (batch + TPB - 1) / TPB;
    mlp_kernel<<<grid, TPB>>>(x, W0, b0, W1, b1, W2, b2, W3, b3, out, batch);
}

// round 4
// speedup vs baseline: 3.3252x; 1.4422x over previous
#include <cuda_runtime.h>

// MLP 64->4->8->8->32, sigmoid each layer, fp32, batch 1M (384MB traffic).
// All warp-local dataflow (no __syncthreads in the hot path):
//  - layer 0 in the coalesced-load domain: W0 fragment in regs, 2-stage
//    shfl_xor reduce, 4-frag partial sums through bank-tuned smem (psum)
//  - layers 1-2 per-row, weights broadcast from smem
//  - layer 3 in the coalesced-store domain: h2 exchanged via smem,
//    W3 repacked (stride 20 words) for conflict-free lane-distinct reads
// 32 warps/SM target: smem ~19.5KB/block, <=64 regs via launch_bounds(128,8).

#define TPB 128

__device__ __forceinline__ float sigmoidf_fast(float x) {
    return __fdividef(1.0f, 1.0f + __expf(-x));
}

__device__ __forceinline__ float dot4(float4 a, float4 b) {
    float s = a.x * b.x;
    s = fmaf(a.y, b.y, s);
    s = fmaf(a.z, b.z, s);
    s = fmaf(a.w, b.w, s);
    return s;
}

__global__ void __launch_bounds__(TPB, 8)
mlp_kernel(const float* __restrict__ x,
           const float* __restrict__ W0, const float* __restrict__ b0,
           const float* __restrict__ W1, const float* __restrict__ b1,
           const float* __restrict__ W2, const float* __restrict__ b2,
           const float* __restrict__ W3, const float* __restrict__ b3,
           float* __restrict__ out, int batch)
{
    // psum: per row 4 float4 partials at +g*4, row stride 20 words (bank-tuned)
    __shared__ __align__(16) float psum[TPB * 20];     // 10240 B
    // h2s: per row 8 floats, row stride 12 words (bank-tuned)
    __shared__ __align__(16) float h2s[TPB * 12];      // 6144 B
    __shared__ __align__(16) float sW1[32];
    __shared__ __align__(16) float sW2[64];
    __shared__ __align__(16) float sW3p[32 * 20];      // repacked, stride 20
    __shared__ __align__(16) float sB0[4];
    __shared__ float sB1[8], sB2[8], sB3[32];

    const int tid  = threadIdx.x;
    const int lane = tid & 31;
    const int wid  = tid >> 5;

    // ---- cooperative weight load ----
    if (tid < 64)       sW2[tid]        = W2[tid];
    else if (tid < 96)  sW1[tid - 64]   = W1[tid - 64];
    else if (tid < 104) sB1[tid - 96]   = b1[tid - 96];
    else if (tid < 112) sB2[tid - 104]  = b2[tid - 104];
    else if (tid < 116) sB0[tid - 112]  = b0[tid - 112];
    if (tid < 32) {
        sB3[tid] = b3[tid];
        // W3 row j stored at repacked row' = (j&3)*8 + (j>>2), stride 20 words
        int rp = (tid & 3) * 8 + (tid >> 2);
        #pragma unroll
        for (int k = 0; k < 8; ++k) sW3p[rp * 20 + k] = W3[tid * 8 + k];
    }
    __syncthreads();

    const int warpRow = (blockIdx.x * (TPB / 32) + wid) * 32;
    if (warpRow >= batch) return;           // whole-warp exit only

    // ---- W0 fragment in registers: this lane's 16-float column group ----
    const int c = lane & 15;
    const float4 w0f0 = __ldg((const float4*)W0 + c);
    const float4 w0f1 = __ldg((const float4*)(W0 + 64) + c);
    const float4 w0f2 = __ldg((const float4*)(W0 + 128) + c);
    const float4 w0f3 = __ldg((const float4*)(W0 + 192) + c);

    const float4* __restrict__ xw = (const float4*)x + (size_t)warpRow * 16;
    const int lim4 = batch * 16 - warpRow * 16;   // remaining float4 of x
    const int prow = wid * 32;                    // this warp's psum row base

    // writer lanes: lane%4==0 -> (row = 2i + lane>>4, group g = (lane>>2)&3)
    const bool wr = ((lane & 3) == 0);
    const int wbase = (prow + (lane >> 4)) * 20 + ((lane >> 2) & 3) * 4;

    // ---- layer 0 in load domain ----
    #pragma unroll
    for (int i = 0; i < 16; ++i) {
        int gi = i * 32 + lane;
        float4 v = make_float4(0.f, 0.f, 0.f, 0.f);
        if (gi < lim4) v = __ldcs(&xw[gi]);          // coalesced LDG.128
        float p0 = dot4(v, w0f0);
        float p1 = dot4(v, w0f1);
        float p2 = dot4(v, w0f2);
        float p3 = dot4(v, w0f3);
        p0 += __shfl_xor_sync(0xffffffffu, p0, 1);
        p1 += __shfl_xor_sync(0xffffffffu, p1, 1);
        p2 += __shfl_xor_sync(0xffffffffu, p2, 1);
        p3 += __shfl_xor_sync(0xffffffffu, p3, 1);
        p0 += __shfl_xor_sync(0xffffffffu, p0, 2);
        p1 += __shfl_xor_sync(0xffffffffu, p1, 2);
        p2 += __shfl_xor_sync(0xffffffffu, p2, 2);
        p3 += __shfl_xor_sync(0xffffffffu, p3, 2);
        if (wr)
            *(float4*)&psum[wbase + i * 40] = make_float4(p0, p1, p2, p3);
    }
    __syncwarp();

    // ---- per-row: finish layer 0, layers 1-2 ----
    float4 s0 = *(const float4*)&psum[tid * 20];
    float4 s1 = *(const float4*)&psum[tid * 20 + 4];
    float4 s2 = *(const float4*)&psum[tid * 20 + 8];
    float4 s3 = *(const float4*)&psum[tid * 20 + 12];
    float4 h0;
    h0.x = sigmoidf_fast(s0.x + s1.x + s2.x + s3.x + sB0[0]);
    h0.y = sigmoidf_fast(s0.y + s1.y + s2.y + s3.y + sB0[1]);
    h0.z = sigmoidf_fast(s0.z + s1.z + s2.z + s3.z + sB0[2]);
    h0.w = sigmoidf_fast(s0.w + s1.w + s2.w + s3.w + sB0[3]);

    float h1[8];
    #pragma unroll
    for (int j = 0; j < 8; ++j) {
        float4 w = *(const float4*)&sW1[j * 4];       // broadcast LDS
        h1[j] = sigmoidf_fast(sB1[j] + dot4(h0, w));
    }
    float4 ha = make_float4(h1[0], h1[1], h1[2], h1[3]);
    float4 hb = make_float4(h1[4], h1[5], h1[6], h1[7]);

    float h2[8];
    #pragma unroll
    for (int j = 0; j < 8; ++j) {
        float4 wa = *(const float4*)&sW2[j * 8];
        float4 wb = *(const float4*)&sW2[j * 8 + 4];
        h2[j] = sigmoidf_fast(sB2[j] + dot4(ha, wa) + dot4(hb, wb));
    }

    *(float4*)&h2s[tid * 12]     = make_float4(h2[0], h2[1], h2[2], h2[3]);
    *(float4*)&h2s[tid * 12 + 4] = make_float4(h2[4], h2[5], h2[6], h2[7]);
    __syncwarp();

    // ---- layer 3 in coalesced store domain ----
    float4* __restrict__ ow = (float4*)out + (size_t)warpRow * 8;
    const int olim = batch * 8 - warpRow * 8;
    const int c4 = lane & 7;
    #pragma unroll
    for (int k = 0; k < 8; ++k) {
        int gi = k * 32 + lane;
        int rl = prow + (gi >> 3);                    // local row owning gi
        float4 ra = *(const float4*)&h2s[rl * 12];
        float4 rb = *(const float4*)&h2s[rl * 12 + 4];
        float o[4];
        #pragma unroll
        for (int kk = 0; kk < 4; ++kk) {
            int rp = kk * 8 + c4;                     // repacked W3 row
            float4 wa = *(const float4*)&sW3p[rp * 20];
            float4 wb = *(const float4*)&sW3p[rp * 20 + 4];
            o[kk] = sigmoidf_fast(sB3[c4 * 4 + kk] + dot4(ra, wa) + dot4(rb, wb));
        }
        if (gi < olim)
            __stcs(&ow[gi], make_float4(o[0], o[1], o[2], o[3]));
    }
}

extern "C" void kernel_launch(void* const* d_in, const int* in_sizes, int n_in,
                              void* d_out, int out_size)
{
    const float* x  = (const float*)d_in[0];
    const float* W0 = (const float*)d_in[1];
    const float* b0 = (const float*)d_in[2];
    const float* W1 = (const float*)d_in[3];
    const float* b1 = (const float*)d_in[4];
    const float* W2 = (const float*)d_in[5];
    const float* b2 = (const float*)d_in[6];
    const float* W3 = (const float*)d_in[7];
    const float* b3 = (const float*)d_in[8];
    float* out = (float*)d_out;

    int batch = in_sizes[0] / 64;
    int grid = (batch + TPB - 1) / TPB;
    mlp_kernel<<<grid, TPB>>>(x, W0, b0, W1, b1, W2, b2, W3, b3, out, batch);
}

// round 5
// speedup vs baseline: 3.6560x; 1.0995x over previous
#include <cuda_runtime.h>

// MLP 64->4->8->8->32, sigmoid each layer, fp32, batch 1M (384MB traffic).
// L1/MIO-pipe-bound; this revision minimizes wavefronts per row:
//  - layer 0 in the coalesced-load domain: W0 fragment in regs, 3-shuffle
//    reduce-scatter (butterfly that reduces AND distributes), then one
//    conflict-free scalar STS per iteration into a transposed psum
//    (psum[k][row], k-stride 34 words: bank = 2k+row, all-distinct)
//  - per-row gather: 16 scalar LDS (lanes differ by 1 word, conflict-free)
//  - layers 1-2 per-row, weights broadcast from smem
//  - layer 3 in the coalesced-store domain, W3 repacked stride 20
// Warp-local producers/consumers only -> __syncwarp, no hot-path barriers.

#define TPB 128
#define PK 34                 // psum k-stride (words)
#define PSUM_WARP (16 * PK)   // floats per warp region = 544

__device__ __forceinline__ float sigmoidf_fast(float x) {
    return __fdividef(1.0f, 1.0f + __expf(-x));
}

__device__ __forceinline__ float dot4(float4 a, float4 b) {
    float s = a.x * b.x;
    s = fmaf(a.y, b.y, s);
    s = fmaf(a.z, b.z, s);
    s = fmaf(a.w, b.w, s);
    return s;
}

__global__ void __launch_bounds__(TPB, 8)
mlp_kernel(const float* __restrict__ x,
           const float* __restrict__ W0, const float* __restrict__ b0,
           const float* __restrict__ W1, const float* __restrict__ b1,
           const float* __restrict__ W2, const float* __restrict__ b2,
           const float* __restrict__ W3, const float* __restrict__ b3,
           float* __restrict__ out, int batch)
{
    __shared__ __align__(16) float psum[4 * PSUM_WARP];  // 8704 B
    __shared__ __align__(16) float h2s[TPB * 12];        // 6144 B
    __shared__ __align__(16) float sW1[32];
    __shared__ __align__(16) float sW2[64];
    __shared__ __align__(16) float sW3p[32 * 20];        // repacked, stride 20
    __shared__ __align__(16) float sB0[4];
    __shared__ float sB1[8], sB2[8], sB3[32];

    const int tid  = threadIdx.x;
    const int lane = tid & 31;
    const int wid  = tid >> 5;

    // ---- cooperative weight load ----
    if (tid < 64)       sW2[tid]        = W2[tid];
    else if (tid < 96)  sW1[tid - 64]   = W1[tid - 64];
    else if (tid < 104) sB1[tid - 96]   = b1[tid - 96];
    else if (tid < 112) sB2[tid - 104]  = b2[tid - 104];
    else if (tid < 116) sB0[tid - 112]  = b0[tid - 112];
    if (tid < 32) {
        sB3[tid] = b3[tid];
        // W3 row j -> repacked row (j&3)*8 + (j>>2), stride 20 words
        int rp = (tid & 3) * 8 + (tid >> 2);
        #pragma unroll
        for (int k = 0; k < 8; ++k) sW3p[rp * 20 + k] = W3[tid * 8 + k];
    }
    __syncthreads();

    const int warpRow = (blockIdx.x * (TPB / 32) + wid) * 32;
    if (warpRow >= batch) return;          // whole-warp exit only

    // ---- W0 fragment in registers: this lane's 16-float column group ----
    const int c = lane & 15;
    const float4 w0f0 = __ldg((const float4*)W0 + c);
    const float4 w0f1 = __ldg((const float4*)(W0 + 64) + c);
    const float4 w0f2 = __ldg((const float4*)(W0 + 128) + c);
    const float4 w0f3 = __ldg((const float4*)(W0 + 192) + c);

    const float4* __restrict__ xw = (const float4*)x + (size_t)warpRow * 16;
    const int lim4 = batch * 16 - warpRow * 16;    // remaining float4 of x

    const bool b0p = (lane & 1);
    const bool b1p = (lane & 2);
    const int  pw  = wid * PSUM_WARP;              // this warp's psum base
    // store slot: [k = lane&15][row = 2i + (lane>>4)]
    const int  sbase = pw + (lane & 15) * PK + (lane >> 4);

    // ---- layer 0 in load domain: 3-shuffle reduce-scatter per float4 ----
    #pragma unroll
    for (int i = 0; i < 16; ++i) {
        int gi = i * 32 + lane;
        float4 v = make_float4(0.f, 0.f, 0.f, 0.f);
        if (gi < lim4) v = __ldcs(&xw[gi]);        // coalesced LDG.128
        float p0 = dot4(v, w0f0);
        float p1 = dot4(v, w0f1);
        float p2 = dot4(v, w0f2);
        float p3 = dot4(v, w0f3);
        // stage 1 (xor 1): keep outputs with bit0 == lane bit0
        float t0 = __shfl_xor_sync(0xffffffffu, b0p ? p0 : p1, 1);
        float t1 = __shfl_xor_sync(0xffffffffu, b0p ? p2 : p3, 1);
        float u0 = (b0p ? p1 : p0) + t0;           // output idx (lane&1)
        float u1 = (b0p ? p3 : p2) + t1;           // output idx (lane&1)+2
        // stage 2 (xor 2): keep output with bit1 == lane bit1
        float t2 = __shfl_xor_sync(0xffffffffu, b1p ? u0 : u1, 2);
        float r4 = (b1p ? u1 : u0) + t2;           // quad sum of output lane&3
        psum[sbase + 2 * i] = r4;                  // conflict-free scalar STS
    }
    __syncwarp();

    // ---- per-row: finish layer 0 (16 scalar LDS, conflict-free) ----
    float vk[16];
    #pragma unroll
    for (int k = 0; k < 16; ++k) vk[k] = psum[pw + k * PK + lane];
    float4 h0;
    h0.x = sigmoidf_fast(((vk[0] + vk[4])  + (vk[8]  + vk[12])) + sB0[0]);
    h0.y = sigmoidf_fast(((vk[1] + vk[5])  + (vk[9]  + vk[13])) + sB0[1]);
    h0.z = sigmoidf_fast(((vk[2] + vk[6])  + (vk[10] + vk[14])) + sB0[2]);
    h0.w = sigmoidf_fast(((vk[3] + vk[7])  + (vk[11] + vk[15])) + sB0[3]);

    // ---- layer 1: 4 -> 8 (broadcast LDS) ----
    float h1[8];
    #pragma unroll
    for (int j = 0; j < 8; ++j) {
        float4 w = *(const float4*)&sW1[j * 4];
        h1[j] = sigmoidf_fast(sB1[j] + dot4(h0, w));
    }
    float4 ha = make_float4(h1[0], h1[1], h1[2], h1[3]);
    float4 hb = make_float4(h1[4], h1[5], h1[6], h1[7]);

    // ---- layer 2: 8 -> 8 ----
    float h2[8];
    #pragma unroll
    for (int j = 0; j < 8; ++j) {
        float4 wa = *(const float4*)&sW2[j * 8];
        float4 wb = *(const float4*)&sW2[j * 8 + 4];
        h2[j] = sigmoidf_fast(sB2[j] + dot4(ha, wa) + dot4(hb, wb));
    }

    *(float4*)&h2s[tid * 12]     = make_float4(h2[0], h2[1], h2[2], h2[3]);
    *(float4*)&h2s[tid * 12 + 4] = make_float4(h2[4], h2[5], h2[6], h2[7]);
    __syncwarp();

    // ---- layer 3 in coalesced store domain ----
    float4* __restrict__ ow = (float4*)out + (size_t)warpRow * 8;
    const int olim = batch * 8 - warpRow * 8;
    const int c4 = lane & 7;
    const int prow = wid * 32;
    #pragma unroll
    for (int k = 0; k < 8; ++k) {
        int gi = k * 32 + lane;
        int rl = prow + (gi >> 3);                 // local row owning gi
        float4 ra = *(const float4*)&h2s[rl * 12];
        float4 rb = *(const float4*)&h2s[rl * 12 + 4];
        float o[4];
        #pragma unroll
        for (int kk = 0; kk < 4; ++kk) {
            int rp = kk * 8 + c4;                  // repacked W3 row
            float4 wa = *(const float4*)&sW3p[rp * 20];
            float4 wb = *(const float4*)&sW3p[rp * 20 + 4];
            o[kk] = sigmoidf_fast(sB3[c4 * 4 + kk] + dot4(ra, wa) + dot4(rb, wb));
        }
        if (gi < olim)
            __stcs(&ow[gi], make_float4(o[0], o[1], o[2], o[3]));
    }
}

extern "C" void kernel_launch(void* const* d_in, const int* in_sizes, int n_in,
                              void* d_out, int out_size)
{
    const float* x  = (const float*)d_in[0];
    const float* W0 = (const float*)d_in[1];
    const float* b0 = (const float*)d_in[2];
    const float* W1 = (const float*)d_in[3];
    const float* b1 = (const float*)d_in[4];
    const float* W2 = (const float*)d_in[5];
    const float* b2 = (const float*)d_in[6];
    const float* W3 = (const float*)d_in[7];
    const float* b3 = (const float*)d_in[8];
    float* out = (float*)d_out;

    int batch = in_sizes[0] / 64;
    int grid = (batch + TPB - 1) / TPB;
    mlp_kernel<<<grid, TPB>>>(x, W0, b0, W1, b1, W2, b2, W3, b3, out, batch);
}